// round 15
// baseline (speedup 1.0000x reference)
#include <cuda_runtime.h>
#include <cuda_fp16.h>
#include <math.h>

#define TT 150
#define BB 64
#define DD 2000
#define SS 3000
#define EE 100000
#define NBLK 148
#define NTHR 512                         // 16 warps

// ---------------- scratch (__device__ globals; re-initialized every call) ----
__device__ __half g_Pt[(size_t)TT * DD * BB];  // exp(input) fp16, [T][D][B]
__device__ __half g_A[2][SS * BB];             // ping-pong scaled forward scores (fp16)
__device__ float  g_csum[(TT + 1) * BB];       // c_t[b] (fp32)
__device__ float  g_part[2][NBLK][BB];         // per-block partials, parity-buffered
__device__ int    g_cnt[SS];
__device__ int    g_rowptr[SS + 1];
__device__ int    g_cursor[SS];
__device__ int2   g_meta[EE];                  // {from<<11|pdf, exp(w) bits} CSR by to

struct __align__(256) BarLine { unsigned v; unsigned pad[63]; };
__device__ BarLine g_count;
__device__ BarLine g_phase;

// ---------------- #1: exp + transpose input; block 0 zeroes state -----------
__global__ void k_exp_T(const float* __restrict__ in) {
    __shared__ float tile[32][33];
    int t  = blockIdx.z;
    int d0 = blockIdx.x * 32;
    int b0 = blockIdx.y * 32;
    int tx = threadIdx.x, ty = threadIdx.y;
    int d = d0 + tx, b = b0 + ty;
    float v = 0.0f;
    if (d < DD) v = in[((size_t)t * BB + b) * DD + d];
    tile[ty][tx] = __expf(v);
    __syncthreads();
    int dd = d0 + ty, bb = b0 + tx;
    if (dd < DD) g_Pt[((size_t)t * DD + dd) * BB + bb] = __float2half_rn(tile[tx][ty]);

    if (blockIdx.x == 0 && blockIdx.y == 0 && blockIdx.z == 0) {
        int tid = ty * 32 + tx;
        if (tid == 0) { g_count.v = 0; g_phase.v = 0; }
        for (int i = tid; i < SS; i += 1024) { g_cnt[i] = 0; g_cursor[i] = 0; }
        for (int i = tid; i < (TT + 1) * BB; i += 1024) g_csum[i] = 0.0f;
    }
}

// ---------------- #2: A0 init + arc histogram -------------------------------
__global__ void k_init_hist(const float* __restrict__ init_logp,
                            const int* __restrict__ to_state) {
    int i = blockIdx.x * blockDim.x + threadIdx.x;
    if (i < SS * BB) {
        int s = i >> 6;
        g_A[0][i] = __float2half_rn(__expf(init_logp[s]));
    }
    if (i < EE) atomicAdd(&g_cnt[to_state[i]], 1);
}

// ---------------- #3: scan + csum0 (single block) ---------------------------
__global__ void k_scan(const float* __restrict__ init_logp) {
    __shared__ int sh[1024];
    __shared__ float shf[1024];
    int tid = threadIdx.x;
    const int CH = 3;
    int base_i = tid * CH;
    int local[CH];
    int sum = 0;
    #pragma unroll
    for (int j = 0; j < CH; j++) {
        int idx = base_i + j;
        int v = (idx < SS) ? g_cnt[idx] : 0;
        local[j] = sum;
        sum += v;
    }
    sh[tid] = sum;
    __syncthreads();
    for (int off = 1; off < 1024; off <<= 1) {
        int v = (tid >= off) ? sh[tid - off] : 0;
        __syncthreads();
        sh[tid] += v;
        __syncthreads();
    }
    int excl = sh[tid] - sum;
    #pragma unroll
    for (int j = 0; j < CH; j++) {
        int idx = base_i + j;
        if (idx < SS) g_rowptr[idx] = excl + local[j];
    }
    if (tid == 0) g_rowptr[SS] = EE;

    float fs = 0.0f;
    for (int idx = tid; idx < SS; idx += 1024)
        fs += __half2float(__float2half_rn(__expf(init_logp[idx])));
    shf[tid] = fs;
    __syncthreads();
    for (int off = 512; off > 0; off >>= 1) {
        if (tid < off) shf[tid] += shf[tid + off];
        __syncthreads();
    }
    if (tid < BB) g_csum[tid] = shf[0];
}

// ---------------- #4: persistent forward (scatter prologue + recursion) -----
__device__ __forceinline__ int ldcg_b32(const __half* p) {
    int v;
    asm volatile("ld.global.cg.b32 %0, [%1];" : "=r"(v) : "l"(p));
    return v;
}
__device__ __forceinline__ float ldcg_f(const float* p) {
    float v;
    asm volatile("ld.global.cg.f32 %0, [%1];" : "=f"(v) : "l"(p));
    return v;
}
__device__ __forceinline__ void stcg_f(float* p, float v) {
    asm volatile("st.global.cg.f32 [%0], %1;" :: "l"(p), "f"(v));
}

__device__ __forceinline__ void grid_barrier(int tid, unsigned target) {
    __syncthreads();
    if (tid == 0) {
        unsigned old;
        asm volatile("atom.add.acq_rel.gpu.global.u32 %0, [%1], 1;"
                     : "=r"(old) : "l"(&g_count.v) : "memory");
        if (old == NBLK - 1) {
            g_count.v = 0;
            asm volatile("st.release.gpu.global.u32 [%0], %1;"
                         :: "l"(&g_phase.v), "r"(target) : "memory");
        } else {
            unsigned ph;
            asm volatile("ld.acquire.gpu.global.u32 %0, [%1];"
                         : "=r"(ph) : "l"(&g_phase.v) : "memory");
            while (ph < target) {
                __nanosleep(32);
                asm volatile("ld.acquire.gpu.global.u32 %0, [%1];"
                             : "=r"(ph) : "l"(&g_phase.v) : "memory");
            }
        }
    }
    __syncthreads();
}

__global__ void __launch_bounds__(NTHR, 1) k_forward(
        const int* __restrict__ to_state,
        const int* __restrict__ from_state,
        const int* __restrict__ pdf_id,
        const float* __restrict__ trans_logw) {
    int tid  = threadIdx.x;
    int warp = tid >> 5;
    int lane = tid & 31;
    int boff = lane << 1;

    // ---- prologue: grid-parallel CSR scatter ----
    for (int i = blockIdx.x * NTHR + tid; i < EE; i += NBLK * NTHR) {
        int to = to_state[i];
        int p = g_rowptr[to] + atomicAdd(&g_cursor[to], 1);
        int packed = (from_state[i] << 11) | pdf_id[i];
        g_meta[p] = make_int2(packed, __float_as_int(__expf(trans_logw[i])));
    }
    grid_barrier(tid, 1);

    int s_begin = (blockIdx.x * SS) / NBLK;
    int s_end   = ((blockIdx.x + 1) * SS) / NBLK;
    int nw = s_end - s_begin;                   // 20 or 21
    int nwork = (blockIdx.x == 0) ? 12 : 16;    // block0: warps 12-15 reduce csum
    bool worker  = warp < nwork;
    bool reducer = (blockIdx.x == 0) && (warp >= 12);
    int rtid = tid - 12 * 32;                   // 0..127 for warps 12-15

    // worker's state range [ws0, ws1): 1 or 2 states
    int ws0 = 0, ws1 = 0, r0 = 0, r1 = 0, bnd = 0;
    if (worker) {
        ws0 = (warp * nw) / nwork;
        ws1 = ((warp + 1) * nw) / nwork;
        r0  = __ldg(&g_rowptr[s_begin + ws0]);
        r1  = __ldg(&g_rowptr[s_begin + ws1]);
        bnd = (ws1 - ws0 > 1) ? __ldg(&g_rowptr[s_begin + ws0 + 1]) : r1;
    }

    __shared__ float sh[21][BB];
    __shared__ float shred[3][BB];

    for (int t = 0; t < TT; t++) {
        const __half* __restrict__ Ap = g_A[t & 1];
        __half*       __restrict__ An = g_A[(t + 1) & 1];
        const __half* __restrict__ P  = g_Pt + (size_t)t * (DD * BB);

        if (worker) {
            float2 acc0a = make_float2(0.f, 0.f), acc0b = make_float2(0.f, 0.f);
            float2 acc1a = make_float2(0.f, 0.f), acc1b = make_float2(0.f, 0.f);
            int e = r0;
            // ---- unroll 16: batch all loads first (MLP ~32) ----
            for (; e + 16 <= r1; e += 16) {
                int2 m[16];
                #pragma unroll
                for (int j = 0; j < 16; j++) m[j] = __ldg(&g_meta[e + j]);
                int ar[16];
                #pragma unroll
                for (int j = 0; j < 16; j++)
                    ar[j] = ldcg_b32(&Ap[((m[j].x >> 11) << 6) + boff]);
                int pr[16];
                #pragma unroll
                for (int j = 0; j < 16; j++)
                    pr[j] = *(const int*)&P[((m[j].x & 2047) << 6) + boff];
                #pragma unroll
                for (int j = 0; j < 16; j++) {
                    float2 a = __half22float2(*(__half2*)&ar[j]);
                    float2 p = __half22float2(*(__half2*)&pr[j]);
                    float w = __int_as_float(m[j].y);
                    float px = (w * a.x) * p.x;
                    float py = (w * a.y) * p.y;
                    bool in0 = (e + j) < bnd;
                    if (j & 1) {
                        acc0b.x += in0 ? px : 0.f;  acc0b.y += in0 ? py : 0.f;
                        acc1b.x += in0 ? 0.f : px;  acc1b.y += in0 ? 0.f : py;
                    } else {
                        acc0a.x += in0 ? px : 0.f;  acc0a.y += in0 ? py : 0.f;
                        acc1a.x += in0 ? 0.f : px;  acc1a.y += in0 ? 0.f : py;
                    }
                }
            }
            for (; e + 4 <= r1; e += 4) {
                int2 m[4];
                #pragma unroll
                for (int j = 0; j < 4; j++) m[j] = __ldg(&g_meta[e + j]);
                int ar[4];
                #pragma unroll
                for (int j = 0; j < 4; j++)
                    ar[j] = ldcg_b32(&Ap[((m[j].x >> 11) << 6) + boff]);
                int pr[4];
                #pragma unroll
                for (int j = 0; j < 4; j++)
                    pr[j] = *(const int*)&P[((m[j].x & 2047) << 6) + boff];
                #pragma unroll
                for (int j = 0; j < 4; j++) {
                    float2 a = __half22float2(*(__half2*)&ar[j]);
                    float2 p = __half22float2(*(__half2*)&pr[j]);
                    float w = __int_as_float(m[j].y);
                    float px = (w * a.x) * p.x;
                    float py = (w * a.y) * p.y;
                    bool in0 = (e + j) < bnd;
                    acc0a.x += in0 ? px : 0.f;  acc0a.y += in0 ? py : 0.f;
                    acc1a.x += in0 ? 0.f : px;  acc1a.y += in0 ? 0.f : py;
                }
            }
            for (; e < r1; e++) {
                int2 m = __ldg(&g_meta[e]);
                int arr = ldcg_b32(&Ap[((m.x >> 11) << 6) + boff]);
                int prr = *(const int*)&P[((m.x & 2047) << 6) + boff];
                float2 a = __half22float2(*(__half2*)&arr);
                float2 p = __half22float2(*(__half2*)&prr);
                float w = __int_as_float(m.y);
                float px = (w * a.x) * p.x;
                float py = (w * a.y) * p.y;
                bool in0 = e < bnd;
                acc0a.x += in0 ? px : 0.f;  acc0a.y += in0 ? py : 0.f;
                acc1a.x += in0 ? 0.f : px;  acc1a.y += in0 ? 0.f : py;
            }

            int cidx = (t < 2) ? 0 : (t - 1);      // one-step-stale normalizer
            float2 c;
            asm volatile("ld.global.cg.v2.f32 {%0,%1}, [%2];"
                         : "=f"(c.x), "=f"(c.y) : "l"(&g_csum[cidx * BB + boff]));
            float icx = __frcp_rn(c.x), icy = __frcp_rn(c.y);

            // state ws0
            {
                float vx = (acc0a.x + acc0b.x) * icx;
                float vy = (acc0a.y + acc0b.y) * icy;
                __half2 h = __floats2half2_rn(vx, vy);
                int bits = *(int*)&h;
                asm volatile("st.global.cg.b32 [%0], %1;"
                             :: "l"(&An[(s_begin + ws0) * BB + boff]), "r"(bits));
                sh[ws0][boff]     = vx;
                sh[ws0][boff + 1] = vy;
            }
            // state ws0+1 (if present)
            if (ws1 - ws0 > 1) {
                float vx = (acc1a.x + acc1b.x) * icx;
                float vy = (acc1a.y + acc1b.y) * icy;
                __half2 h = __floats2half2_rn(vx, vy);
                int bits = *(int*)&h;
                asm volatile("st.global.cg.b32 [%0], %1;"
                             :: "l"(&An[(s_begin + ws0 + 1) * BB + boff]), "r"(bits));
                sh[ws0 + 1][boff]     = vx;
                sh[ws0 + 1][boff + 1] = vy;
            }
        } else if (reducer && t >= 1 && t <= TT - 2) {
            // c_t = sum over blocks of g_part[t&1][blk][b] (written end of step t-1)
            const float* part = &g_part[t & 1][0][0];
            for (int slot = rtid; slot < 192; slot += 128) {
                int sb = slot & 63, sc = slot >> 6;
                float v = 0.0f;
                int blk0 = sc * 50;
                int blk1 = blk0 + 50; if (blk1 > NBLK) blk1 = NBLK;
                for (int blk = blk0; blk < blk1; blk++)
                    v += ldcg_f(part + blk * BB + sb);
                shred[sc][sb] = v;
            }
            asm volatile("bar.sync 1, 128;" ::: "memory");
            if (rtid < BB)
                stcg_f(&g_csum[t * BB + rtid],
                       shred[0][rtid] + shred[1][rtid] + shred[2][rtid]);
        }
        __syncthreads();
        if (tid < BB) {
            float v = 0.0f;
            for (int w = 0; w < nw; w++) v += sh[w][tid];
            stcg_f(&g_part[(t + 1) & 1][blockIdx.x][tid], v);   // partial of c_{t+1}
        }
        grid_barrier(tid, (unsigned)(t + 2));
    }
}

// ---------------- #5: objf (divisors: c0, c0, c1, ..., c_{T-2}) -------------
__global__ void k_final(const float* __restrict__ final_logp, float* __restrict__ out) {
    __shared__ float red[256];
    __shared__ float red2[256];
    __shared__ float dotlog[BB];
    const __half* At = g_A[TT & 1];
    int b = threadIdx.x & 63;
    int c = threadIdx.x >> 6;
    float acc = 0.0f;
    for (int s = c; s < SS; s += 4)
        acc += __half2float(At[s * BB + b]) * expf(final_logp[s]);
    red[threadIdx.x] = acc;

    float lp = 0.0f;
    for (int t = 1 + c; t <= TT - 2; t += 4) lp += logf(g_csum[t * BB + b]);
    red2[threadIdx.x] = lp;
    __syncthreads();
    if (c == 0) {
        float dot = red[b] + red[64 + b] + red[128 + b] + red[192 + b];
        dotlog[b] = logf(dot) + 2.0f * logf(g_csum[b])
                  + red2[b] + red2[64 + b] + red2[128 + b] + red2[192 + b];
    }
    __syncthreads();
    if (threadIdx.x == 0) {
        float s = 0.0f;
        for (int bb = 0; bb < BB; bb++) s += dotlog[bb];
        out[0] = s;
    }
}

// ---------------- launch -----------------------------------------------------
extern "C" void kernel_launch(void* const* d_in, const int* in_sizes, int n_in,
                              void* d_out, int out_size) {
    const float* input      = (const float*)d_in[0];
    const float* trans_logw = (const float*)d_in[1];
    const float* init_logp  = (const float*)d_in[2];
    const float* final_logp = (const float*)d_in[3];
    const int*   from_state = (const int*)d_in[4];
    const int*   to_state   = (const int*)d_in[5];
    const int*   pdf_id     = (const int*)d_in[6];
    float* out = (float*)d_out;

    dim3 gT((DD + 31) / 32, BB / 32, TT);
    k_exp_T<<<gT, dim3(32, 32)>>>(input);                              // 1
    k_init_hist<<<(SS * BB + 255) / 256, 256>>>(init_logp, to_state);  // 2
    k_scan<<<1, 1024>>>(init_logp);                                    // 3
    k_forward<<<NBLK, NTHR>>>(to_state, from_state, pdf_id, trans_logw); // 4 (profiled)
    k_final<<<1, 256>>>(final_logp, out);                              // 5
}

// round 16
// speedup vs baseline: 1.3767x; 1.3767x over previous
#include <cuda_runtime.h>
#include <cuda_fp16.h>
#include <math.h>

#define TT 150
#define BB 64
#define DD 2000
#define SS 3000
#define EE 100000
#define NBLK 148
#define NTHR 768                         // 24 warps; workers = states/block (20-21)

// ---------------- scratch (__device__ globals; re-initialized every call) ----
__device__ __half g_Pt[(size_t)TT * DD * BB];  // exp(input) fp16, [T][D][B]
__device__ __half g_A[2][SS * BB];             // ping-pong scaled forward scores (fp16)
__device__ float  g_q[TT * BB];                // per-step normalizers (fp32)
__device__ float  g_cntw[DD];                  // sum of exp(w) per pdf
__device__ int    g_cnt[SS];
__device__ int    g_rowptr[SS + 1];
__device__ int    g_cursor[SS];
__device__ int2   g_meta[EE];                  // {from<<11|pdf, exp(w) bits} CSR by to

struct __align__(256) BarLine { unsigned v; unsigned pad[63]; };
__device__ BarLine g_count;
__device__ BarLine g_phase;

// ---------------- #1: exp + transpose input; block 0 zeroes state -----------
__global__ void k_exp_T(const float* __restrict__ in) {
    __shared__ float tile[32][33];
    int t  = blockIdx.z;
    int d0 = blockIdx.x * 32;
    int b0 = blockIdx.y * 32;
    int tx = threadIdx.x, ty = threadIdx.y;
    int d = d0 + tx, b = b0 + ty;
    float v = 0.0f;
    if (d < DD) v = in[((size_t)t * BB + b) * DD + d];
    tile[ty][tx] = __expf(v);
    __syncthreads();
    int dd = d0 + ty, bb = b0 + tx;
    if (dd < DD) g_Pt[((size_t)t * DD + dd) * BB + bb] = __float2half_rn(tile[tx][ty]);

    if (blockIdx.x == 0 && blockIdx.y == 0 && blockIdx.z == 0) {
        int tid = ty * 32 + tx;
        if (tid == 0) { g_count.v = 0; g_phase.v = 0; }
        for (int i = tid; i < SS; i += 1024) { g_cnt[i] = 0; g_cursor[i] = 0; }
        for (int i = tid; i < DD; i += 1024) g_cntw[i] = 0.0f;
    }
}

// ---------------- #2: A0 init (scaled by S) + histograms --------------------
__global__ void k_init_hist(const float* __restrict__ init_logp,
                            const int* __restrict__ to_state,
                            const int* __restrict__ pdf_id,
                            const float* __restrict__ trans_logw) {
    int i = blockIdx.x * blockDim.x + threadIdx.x;
    if (i < SS * BB) {
        int s = i >> 6;
        g_A[0][i] = __float2half_rn(__expf(init_logp[s]) * (float)SS);
    }
    if (i < EE) {
        atomicAdd(&g_cnt[to_state[i]], 1);
        atomicAdd(&g_cntw[pdf_id[i]], __expf(trans_logw[i]));
    }
}

// ---------------- #3: rowptr scan (single block) ----------------------------
__global__ void k_scan(const float* __restrict__ init_logp) {
    __shared__ int sh[1024];
    int tid = threadIdx.x;
    const int CH = 3;
    int base_i = tid * CH;
    int local[CH];
    int sum = 0;
    #pragma unroll
    for (int j = 0; j < CH; j++) {
        int idx = base_i + j;
        int v = (idx < SS) ? g_cnt[idx] : 0;
        local[j] = sum;
        sum += v;
    }
    sh[tid] = sum;
    __syncthreads();
    for (int off = 1; off < 1024; off <<= 1) {
        int v = (tid >= off) ? sh[tid - off] : 0;
        __syncthreads();
        sh[tid] += v;
        __syncthreads();
    }
    int excl = sh[tid] - sum;
    #pragma unroll
    for (int j = 0; j < CH; j++) {
        int idx = base_i + j;
        if (idx < SS) g_rowptr[idx] = excl + local[j];
    }
    if (tid == 0) g_rowptr[SS] = EE;
}

// ---------------- #4: persistent forward -------------------------------------
__device__ __forceinline__ int ldcg_b32(const __half* p) {
    int v;
    asm volatile("ld.global.cg.b32 %0, [%1];" : "=r"(v) : "l"(p));
    return v;
}

__device__ __forceinline__ void grid_barrier(int tid, unsigned target) {
    __syncthreads();
    if (tid == 0) {
        unsigned old;
        asm volatile("atom.add.acq_rel.gpu.global.u32 %0, [%1], 1;"
                     : "=r"(old) : "l"(&g_count.v) : "memory");
        if (old == NBLK - 1) {
            g_count.v = 0;
            asm volatile("st.release.gpu.global.u32 [%0], %1;"
                         :: "l"(&g_phase.v), "r"(target) : "memory");
        } else {
            unsigned ph;
            asm volatile("ld.acquire.gpu.global.u32 %0, [%1];"
                         : "=r"(ph) : "l"(&g_phase.v) : "memory");
            while (ph < target) {
                __nanosleep(32);
                asm volatile("ld.acquire.gpu.global.u32 %0, [%1];"
                             : "=r"(ph) : "l"(&g_phase.v) : "memory");
            }
        }
    }
    __syncthreads();
}

__global__ void __launch_bounds__(NTHR, 1) k_forward(
        const int* __restrict__ to_state,
        const int* __restrict__ from_state,
        const int* __restrict__ pdf_id,
        const float* __restrict__ trans_logw) {
    int tid  = threadIdx.x;
    int warp = tid >> 5;
    int lane = tid & 31;
    int boff = lane << 1;

    __shared__ float shq[24][BB];

    // ---- prologue A: CSR scatter (1 arc per thread; 148*768 >= E) ----
    {
        int i = blockIdx.x * NTHR + tid;
        if (i < EE) {
            int to = to_state[i];
            int p = g_rowptr[to] + atomicAdd(&g_cursor[to], 1);
            int packed = (from_state[i] << 11) | pdf_id[i];
            g_meta[p] = make_int2(packed, __float_as_int(__expf(trans_logw[i])));
        }
    }
    // ---- prologue B: q_t[b] = (1/S) * sum_d cntw[d]*P_t[d,b] ----
    for (int tq = blockIdx.x; tq < TT; tq += NBLK) {
        const __half* P = g_Pt + (size_t)tq * (DD * BB);
        float2 acc = make_float2(0.f, 0.f);
        for (int d = warp; d < DD; d += 24) {
            float cw = __ldg(&g_cntw[d]);
            int pv = *(const int*)&P[d * BB + boff];
            float2 p = __half22float2(*(__half2*)&pv);
            acc.x = fmaf(cw, p.x, acc.x);
            acc.y = fmaf(cw, p.y, acc.y);
        }
        shq[warp][boff]     = acc.x;
        shq[warp][boff + 1] = acc.y;
        __syncthreads();
        if (tid < BB) {
            float v = 0.0f;
            #pragma unroll
            for (int w = 0; w < 24; w++) v += shq[w][tid];
            g_q[tq * BB + tid] = v * (1.0f / (float)SS);
        }
        __syncthreads();
    }
    grid_barrier(tid, 1);

    int s_begin = (blockIdx.x * SS) / NBLK;
    int s_end   = ((blockIdx.x + 1) * SS) / NBLK;
    int nw = s_end - s_begin;                   // 20 or 21
    int s = s_begin + warp;
    bool active = warp < nw;

    int r0 = 0, r1 = 0;
    if (active) { r0 = __ldg(&g_rowptr[s]); r1 = __ldg(&g_rowptr[s + 1]); }

    for (int t = 0; t < TT; t++) {
        if (active) {
            const __half* __restrict__ Ap = g_A[t & 1];
            __half*       __restrict__ An = g_A[(t + 1) & 1];
            const __half* __restrict__ P  = g_Pt + (size_t)t * (DD * BB);

            float2 q = *(const float2*)&g_q[t * BB + boff];   // read-only, L1 ok
            float2 invc = make_float2(__frcp_rn(q.x), __frcp_rn(q.y));

            float2 acc0 = make_float2(0.f, 0.f);
            float2 acc1 = make_float2(0.f, 0.f);
            int e = r0;
            // ---- unroll 8: batch loads first (round-13 proven shape) ----
            for (; e + 8 <= r1; e += 8) {
                int2 m[8];
                #pragma unroll
                for (int j = 0; j < 8; j++) m[j] = __ldg(&g_meta[e + j]);
                int ar[8];
                #pragma unroll
                for (int j = 0; j < 8; j++)
                    ar[j] = ldcg_b32(&Ap[((m[j].x >> 11) << 6) + boff]);
                int pr[8];
                #pragma unroll
                for (int j = 0; j < 8; j++)
                    pr[j] = *(const int*)&P[((m[j].x & 2047) << 6) + boff];
                #pragma unroll
                for (int j = 0; j < 8; j++) {
                    float2 a = __half22float2(*(__half2*)&ar[j]);
                    float2 p = __half22float2(*(__half2*)&pr[j]);
                    float w = __int_as_float(m[j].y);
                    if (j & 1) {
                        acc1.x = fmaf(w * a.x, p.x, acc1.x);
                        acc1.y = fmaf(w * a.y, p.y, acc1.y);
                    } else {
                        acc0.x = fmaf(w * a.x, p.x, acc0.x);
                        acc0.y = fmaf(w * a.y, p.y, acc0.y);
                    }
                }
            }
            for (; e + 4 <= r1; e += 4) {
                int2 m[4];
                #pragma unroll
                for (int j = 0; j < 4; j++) m[j] = __ldg(&g_meta[e + j]);
                int ar[4];
                #pragma unroll
                for (int j = 0; j < 4; j++)
                    ar[j] = ldcg_b32(&Ap[((m[j].x >> 11) << 6) + boff]);
                int pr[4];
                #pragma unroll
                for (int j = 0; j < 4; j++)
                    pr[j] = *(const int*)&P[((m[j].x & 2047) << 6) + boff];
                #pragma unroll
                for (int j = 0; j < 4; j++) {
                    float2 a = __half22float2(*(__half2*)&ar[j]);
                    float2 p = __half22float2(*(__half2*)&pr[j]);
                    float w = __int_as_float(m[j].y);
                    if (j & 1) {
                        acc1.x = fmaf(w * a.x, p.x, acc1.x);
                        acc1.y = fmaf(w * a.y, p.y, acc1.y);
                    } else {
                        acc0.x = fmaf(w * a.x, p.x, acc0.x);
                        acc0.y = fmaf(w * a.y, p.y, acc0.y);
                    }
                }
            }
            for (; e < r1; e++) {
                int2 m = __ldg(&g_meta[e]);
                int arr = ldcg_b32(&Ap[((m.x >> 11) << 6) + boff]);
                int prr = *(const int*)&P[((m.x & 2047) << 6) + boff];
                float2 a = __half22float2(*(__half2*)&arr);
                float2 p = __half22float2(*(__half2*)&prr);
                float w = __int_as_float(m.y);
                acc0.x = fmaf(w * a.x, p.x, acc0.x);
                acc0.y = fmaf(w * a.y, p.y, acc0.y);
            }

            float vx = (acc0.x + acc1.x) * invc.x;
            float vy = (acc0.y + acc1.y) * invc.y;
            __half2 h = __floats2half2_rn(vx, vy);
            int bits = *(int*)&h;
            asm volatile("st.global.cg.b32 [%0], %1;"
                         :: "l"(&An[s * BB + boff]), "r"(bits));
        }
        grid_barrier(tid, (unsigned)(t + 2));
    }
}

// ---------------- #5: objf = sum_b [ log(A_T.F) - log S + sum_t log q_t ] ---
__global__ void k_final(const float* __restrict__ final_logp, float* __restrict__ out) {
    __shared__ float red[256];
    __shared__ float red2[256];
    __shared__ float dotlog[BB];
    const __half* At = g_A[TT & 1];
    int b = threadIdx.x & 63;
    int c = threadIdx.x >> 6;
    float acc = 0.0f;
    for (int s = c; s < SS; s += 4)
        acc += __half2float(At[s * BB + b]) * expf(final_logp[s]);
    red[threadIdx.x] = acc;

    float lp = 0.0f;
    for (int t = c; t < TT; t += 4) lp += logf(g_q[t * BB + b]);
    red2[threadIdx.x] = lp;
    __syncthreads();
    if (c == 0) {
        float dot = red[b] + red[64 + b] + red[128 + b] + red[192 + b];
        dotlog[b] = logf(dot) - logf((float)SS)
                  + red2[b] + red2[64 + b] + red2[128 + b] + red2[192 + b];
    }
    __syncthreads();
    if (threadIdx.x == 0) {
        float s = 0.0f;
        for (int bb = 0; bb < BB; bb++) s += dotlog[bb];
        out[0] = s;
    }
}

// ---------------- launch -----------------------------------------------------
extern "C" void kernel_launch(void* const* d_in, const int* in_sizes, int n_in,
                              void* d_out, int out_size) {
    const float* input      = (const float*)d_in[0];
    const float* trans_logw = (const float*)d_in[1];
    const float* init_logp  = (const float*)d_in[2];
    const float* final_logp = (const float*)d_in[3];
    const int*   from_state = (const int*)d_in[4];
    const int*   to_state   = (const int*)d_in[5];
    const int*   pdf_id     = (const int*)d_in[6];
    float* out = (float*)d_out;

    dim3 gT((DD + 31) / 32, BB / 32, TT);
    k_exp_T<<<gT, dim3(32, 32)>>>(input);                              // 1
    k_init_hist<<<(SS * BB + 255) / 256, 256>>>(init_logp, to_state,
                                                pdf_id, trans_logw);   // 2
    k_scan<<<1, 1024>>>(init_logp);                                    // 3
    k_forward<<<NBLK, NTHR>>>(to_state, from_state, pdf_id, trans_logw); // 4 (profiled)
    k_final<<<1, 256>>>(final_logp, out);                              // 5
}